// round 9
// baseline (speedup 1.0000x reference)
#include <cuda_runtime.h>
#include <cuda_fp16.h>
#include <stdint.h>

#define LUT_N 35937                   // 33^3 entries per channel
#define CH_STRIDE 35937
#define HW (1080 * 1920)
#define HW2 (HW / 2)                  // float2 groups per plane
#define NBATCH 4
#define NV2 (NBATCH * HW2)            // 4,147,200 float2 groups
#define NBLOCKS 152                   // one persistent CTA per SM
#define NTHREADS 512                  // 128-reg budget -> room for 2 burst buffers
#define STRIDE (NBLOCKS * NTHREADS)
#define SMEM_BYTES (LUT_N * 4 + LUT_N * 2)   // 215,622 B  (< 227 KB)

__device__ __forceinline__ float2 h2f(unsigned int u) {
    __half2 h = *reinterpret_cast<__half2*>(&u);
    return __half22float2(h);
}
__device__ __forceinline__ float uh2f(unsigned short u) {
    return __half2float(__ushort_as_half(u));
}
__device__ __forceinline__ float2 lerp2(float2 a, float2 b, float f) {
    return make_float2(fmaf(f, b.x - a.x, a.x), fmaf(f, b.y - a.y, a.y));
}

// index/frac for one pixel
#define PIXIDX(rv, gv, bv, qq, frv, fgv, fbv) do {                         \
    float sr_ = __saturatef(rv) * 32.0f;                                   \
    float sg_ = __saturatef(gv) * 32.0f;                                   \
    float sb_ = __saturatef(bv) * 32.0f;                                   \
    int ri_ = min((int)sr_, 31);                                           \
    int gi_ = min((int)sg_, 31);                                           \
    int bi_ = min((int)sb_, 31);                                           \
    frv = sr_ - (float)ri_; fgv = sg_ - (float)gi_; fbv = sb_ - (float)bi_;\
    qq = (bi_ * 33 + gi_) * 33 + ri_;                                      \
} while (0)

// 16 gathers for one pixel (8 corners x {c01, c2})
#define GATHER(aT, zT, qq) do {                                            \
    aT[0] = c01[qq];          aT[1] = c01[qq + 1];                         \
    aT[2] = c01[qq + 33];     aT[3] = c01[qq + 34];                        \
    aT[4] = c01[qq + 1089];   aT[5] = c01[qq + 1090];                      \
    aT[6] = c01[qq + 1122];   aT[7] = c01[qq + 1123];                      \
    zT[0] = c2u[qq];          zT[1] = c2u[qq + 1];                         \
    zT[2] = c2u[qq + 33];     zT[3] = c2u[qq + 34];                        \
    zT[4] = c2u[qq + 1089];   zT[5] = c2u[qq + 1090];                      \
    zT[6] = c2u[qq + 1122];   zT[7] = c2u[qq + 1123];                      \
} while (0)

// trilinear math for one pixel from a gathered burst
#define MATHPX(aT, zT, frv, fgv, fbv, O0, O1, O2) do {                     \
    float2 e00 = lerp2(h2f(aT[0]), h2f(aT[1]), frv);                       \
    float2 e01 = lerp2(h2f(aT[2]), h2f(aT[3]), frv);                       \
    float2 e10 = lerp2(h2f(aT[4]), h2f(aT[5]), frv);                       \
    float2 e11 = lerp2(h2f(aT[6]), h2f(aT[7]), frv);                       \
    float2 eg0 = lerp2(e00, e01, fgv);                                     \
    float2 eg1 = lerp2(e10, e11, fgv);                                     \
    float2 ec  = lerp2(eg0, eg1, fbv);                                     \
    float z0_ = uh2f(zT[0]), z1_ = uh2f(zT[1]);                            \
    float z2_ = uh2f(zT[2]), z3_ = uh2f(zT[3]);                            \
    float z4_ = uh2f(zT[4]), z5_ = uh2f(zT[5]);                            \
    float z6_ = uh2f(zT[6]), z7_ = uh2f(zT[7]);                            \
    float s00_ = fmaf(frv, z1_ - z0_, z0_);                                \
    float s01_ = fmaf(frv, z3_ - z2_, z2_);                                \
    float s10_ = fmaf(frv, z5_ - z4_, z4_);                                \
    float s11_ = fmaf(frv, z7_ - z6_, z6_);                                \
    float sg0_ = fmaf(fgv, s01_ - s00_, s00_);                             \
    float sg1_ = fmaf(fgv, s11_ - s10_, s10_);                             \
    O0 = ec.x; O1 = ec.y; O2 = fmaf(fbv, sg1_ - sg0_, sg0_);               \
} while (0)

// One pipeline phase: issue NXT's burst + prefetch, then math/store CUR.
#define PHASE(aC, zC, frC, fgC, fbC, aN, zN, frN, fgN, fbN) do {           \
    int v_fut = v_nxt + STRIDE;                                           \
    bool more_fut = v_fut < NV2;                                          \
    if (more) {                                                           \
        int qn0_, qn1_;                                                   \
        PIXIDX(rn.x, gn.x, bn.x, qn0_, frN[0], fgN[0], fbN[0]);           \
        PIXIDX(rn.y, gn.y, bn.y, qn1_, frN[1], fgN[1], fbN[1]);           \
        GATHER(aN[0], zN[0], qn0_);                                       \
        GATHER(aN[1], zN[1], qn1_);                                       \
        if (more_fut) {                                                   \
            int bf_ = v_fut / HW2;                                        \
            int jf_ = v_fut - bf_ * HW2;                                  \
            const float2* xpf_ = reinterpret_cast<const float2*>(x)       \
                                 + (size_t)bf_ * 3 * HW2;                 \
            rn = __ldcs(xpf_ + jf_);                                      \
            gn = __ldcs(xpf_ + jf_ + HW2);                                \
            bn = __ldcs(xpf_ + jf_ + 2 * HW2);                            \
        }                                                                 \
    }                                                                     \
    {                                                                     \
        int bc_ = v_cur / HW2;                                            \
        int jc_ = v_cur - bc_ * HW2;                                      \
        float2* op_ = reinterpret_cast<float2*>(out)                      \
                      + (size_t)bc_ * 3 * HW2;                            \
        float o0_[2], o1_[2], o2_[2];                                     \
        MATHPX(aC[0], zC[0], frC[0], fgC[0], fbC[0], o0_[0], o1_[0], o2_[0]); \
        MATHPX(aC[1], zC[1], frC[1], fgC[1], fbC[1], o0_[1], o1_[1], o2_[1]); \
        __stcs(op_ + jc_,           make_float2(o0_[0], o0_[1]));         \
        __stcs(op_ + jc_ + HW2,     make_float2(o1_[0], o1_[1]));         \
        __stcs(op_ + jc_ + 2 * HW2, make_float2(o2_[0], o2_[1]));         \
    }                                                                     \
    if (!more) goto done;                                                 \
    v_cur = v_nxt; v_nxt = v_fut; more = more_fut;                        \
} while (0)

__global__ void __launch_bounds__(NTHREADS, 1)
lut_apply_smem(const float* __restrict__ x, const float* __restrict__ LUT,
               float* __restrict__ out) {
    extern __shared__ unsigned char smem[];
    unsigned int*   __restrict__ c01 = reinterpret_cast<unsigned int*>(smem);
    unsigned short* __restrict__ c2u = reinterpret_cast<unsigned short*>(smem + LUT_N * 4);

    // ── Fill SMEM LUT (fp32 -> fp16) ──
    for (int i = threadIdx.x; i < LUT_N; i += NTHREADS) {
        __half2 h = __floats2half2_rn(LUT[i], LUT[i + CH_STRIDE]);
        c01[i] = *reinterpret_cast<unsigned int*>(&h);
        __half h2 = __float2half_rn(LUT[i + 2 * CH_STRIDE]);
        c2u[i] = *reinterpret_cast<unsigned short*>(&h2);
    }
    __syncthreads();

    // ── Pipeline state ──
    unsigned int   aA[2][8], aB[2][8];
    unsigned short zA[2][8], zB[2][8];
    float frA[2], fgA[2], fbA[2], frB[2], fgB[2], fbB[2];
    float2 rn, gn, bn;

    int v_cur = blockIdx.x * NTHREADS + threadIdx.x;

    // Prologue: stream x for v_cur, issue burst A
    {
        int b0 = v_cur / HW2;
        int j0 = v_cur - b0 * HW2;
        const float2* xp0 = reinterpret_cast<const float2*>(x) + (size_t)b0 * 3 * HW2;
        rn = __ldcs(xp0 + j0);
        gn = __ldcs(xp0 + j0 + HW2);
        bn = __ldcs(xp0 + j0 + 2 * HW2);
    }
    {
        int q0_, q1_;
        PIXIDX(rn.x, gn.x, bn.x, q0_, frA[0], fgA[0], fbA[0]);
        PIXIDX(rn.y, gn.y, bn.y, q1_, frA[1], fgA[1], fbA[1]);
        GATHER(aA[0], zA[0], q0_);
        GATHER(aA[1], zA[1], q1_);
    }

    int v_nxt = v_cur + STRIDE;
    bool more = v_nxt < NV2;
    if (more) {
        int b1 = v_nxt / HW2;
        int j1 = v_nxt - b1 * HW2;
        const float2* xp1 = reinterpret_cast<const float2*>(x) + (size_t)b1 * 3 * HW2;
        rn = __ldcs(xp1 + j1);
        gn = __ldcs(xp1 + j1 + HW2);
        bn = __ldcs(xp1 + j1 + 2 * HW2);
    }

    while (true) {
        PHASE(aA, zA, frA, fgA, fbA, aB, zB, frB, fgB, fbB);
        PHASE(aB, zB, frB, fgB, fbB, aA, zA, frA, fgA, fbA);
    }
done: ;
}

extern "C" void kernel_launch(void* const* d_in, const int* in_sizes, int n_in,
                              void* d_out, int out_size) {
    const float* x   = (const float*)d_in[0];   // (4,3,1080,1920) fp32
    const float* LUT = (const float*)d_in[1];   // (3,33,33,33) fp32
    float* out = (float*)d_out;

    static bool smem_ok = []() {
        cudaFuncSetAttribute(lut_apply_smem,
                             cudaFuncAttributeMaxDynamicSharedMemorySize,
                             SMEM_BYTES);
        return true;
    }();
    (void)smem_ok;

    lut_apply_smem<<<NBLOCKS, NTHREADS, SMEM_BYTES>>>(x, LUT, out);
}

// round 10
// speedup vs baseline: 1.6554x; 1.6554x over previous
#include <cuda_runtime.h>
#include <cuda_fp16.h>
#include <stdint.h>

#define LUT_N 35937                   // 33^3 entries per channel
#define CH_STRIDE 35937
#define HW (1080 * 1920)
#define HW2 (HW / 2)                  // float2 groups per plane
#define NBATCH 4
#define NV2 (NBATCH * HW2)            // 4,147,200 float2 groups
#define NBLOCKS 152                   // one persistent CTA per SM
#define NTHREADS 1024
#define STRIDE (NBLOCKS * NTHREADS)
// SMEM layout: c01 table (half2 {c0,c1}, 4B/entry) then c2 table (half, 2B/entry)
#define C01_BYTES (LUT_N * 4)                       // 143,748
#define SMEM_BYTES (LUT_N * 4 + LUT_N * 2)          // 215,622 B (< 227 KB)
#define SCRATCH_BYTES ((SMEM_BYTES + 15) & ~15)     // 215,632 (16B-padded)

// Staged fp16 tables, exact SMEM image (built once by pack kernel).
__device__ __align__(16) unsigned char g_staged[SCRATCH_BYTES];

__global__ void pack_lut_kernel(const float* __restrict__ LUT) {
    int i = blockIdx.x * blockDim.x + threadIdx.x;
    if (i >= LUT_N) return;
    __half2 h = __floats2half2_rn(LUT[i], LUT[i + CH_STRIDE]);
    *reinterpret_cast<unsigned int*>(g_staged + 4 * (size_t)i) =
        *reinterpret_cast<unsigned int*>(&h);
    __half h2 = __float2half_rn(LUT[i + 2 * CH_STRIDE]);
    *reinterpret_cast<unsigned short*>(g_staged + C01_BYTES + 2 * (size_t)i) =
        *reinterpret_cast<unsigned short*>(&h2);
}

__device__ __forceinline__ float2 h2f(unsigned int u) {
    __half2 h = *reinterpret_cast<__half2*>(&u);
    return __half22float2(h);
}
__device__ __forceinline__ float2 lerp2(float2 a, float2 b, float f) {
    return make_float2(fmaf(f, b.x - a.x, a.x), fmaf(f, b.y - a.y, a.y));
}

__global__ void __launch_bounds__(NTHREADS, 1)
lut_apply_smem(const float* __restrict__ x, float* __restrict__ out) {
    extern __shared__ unsigned char smem[];
    unsigned int*   __restrict__ c01 = reinterpret_cast<unsigned int*>(smem);
    unsigned short* __restrict__ c2u = reinterpret_cast<unsigned short*>(smem + C01_BYTES);

    int v = blockIdx.x * NTHREADS + threadIdx.x;   // float2-group index

    // ── Streaming prologue FIRST: overlaps DRAM latency with the SMEM fill ──
    int b = v / HW2;
    int j = v - b * HW2;
    const float2* xp = reinterpret_cast<const float2*>(x) + (size_t)b * 3 * HW2;
    float2 r2 = __ldcs(xp + j);
    float2 g2 = __ldcs(xp + j + HW2);
    float2 b2 = __ldcs(xp + j + 2 * HW2);

    // ── SMEM fill: pure 16B memcpy of the staged fp16 image ──
    {
        const uint4* src = reinterpret_cast<const uint4*>(g_staged);
        uint4*       dst = reinterpret_cast<uint4*>(smem);
#pragma unroll 4
        for (int i = threadIdx.x; i < SCRATCH_BYTES / 16; i += NTHREADS)
            dst[i] = __ldg(src + i);
    }
    __syncthreads();

    while (true) {
        int vn = v + STRIDE;
        bool more = vn < NV2;

        float2* op = reinterpret_cast<float2*>(out) + (size_t)b * 3 * HW2;
        int jc = j;

        // ── Prefetch next iteration's streaming triple ──
        float2 nr2, ng2, nb2;
        if (more) {
            int bn = vn / HW2;
            int jn = vn - bn * HW2;
            const float2* xpn = reinterpret_cast<const float2*>(x) + (size_t)bn * 3 * HW2;
            nr2 = __ldcs(xpn + jn);
            ng2 = __ldcs(xpn + jn + HW2);
            nb2 = __ldcs(xpn + jn + 2 * HW2);
            b = bn; j = jn;
        }

        // ── Indices/fracs for both pixels ──
        float rs[2] = { r2.x, r2.y };
        float gs[2] = { g2.x, g2.y };
        float bs[2] = { b2.x, b2.y };
        int   q[2];
        float fr[2], fg[2], fb[2];
#pragma unroll
        for (int i = 0; i < 2; i++) {
            float sr = __saturatef(rs[i]) * 32.0f;
            float sg = __saturatef(gs[i]) * 32.0f;
            float sb = __saturatef(bs[i]) * 32.0f;
            int ri = min((int)sr, 31);
            int gi = min((int)sg, 31);
            int bi = min((int)sb, 31);
            fr[i] = sr - (float)ri;
            fg[i] = sg - (float)gi;
            fb[i] = sb - (float)bi;
            q[i]  = (bi * 33 + gi) * 33 + ri;
        }

        // ── Issue ALL 32 gathers for both pixels before any math ──
        unsigned int   a[2][8];
        unsigned short z[2][8];
#pragma unroll
        for (int t = 0; t < 2; t++) {
            int qq = q[t];
            a[t][0] = c01[qq];          a[t][1] = c01[qq + 1];
            a[t][2] = c01[qq + 33];     a[t][3] = c01[qq + 34];
            a[t][4] = c01[qq + 1089];   a[t][5] = c01[qq + 1090];
            a[t][6] = c01[qq + 1122];   a[t][7] = c01[qq + 1123];
            z[t][0] = c2u[qq];          z[t][1] = c2u[qq + 1];
            z[t][2] = c2u[qq + 33];     z[t][3] = c2u[qq + 34];
            z[t][4] = c2u[qq + 1089];   z[t][5] = c2u[qq + 1090];
            z[t][6] = c2u[qq + 1122];   z[t][7] = c2u[qq + 1123];
        }

        float o0[2], o1[2], o2[2];
#pragma unroll
        for (int t = 0; t < 2; t++) {
            float2 e00 = lerp2(h2f(a[t][0]), h2f(a[t][1]), fr[t]);
            float2 e01 = lerp2(h2f(a[t][2]), h2f(a[t][3]), fr[t]);
            float2 e10 = lerp2(h2f(a[t][4]), h2f(a[t][5]), fr[t]);
            float2 e11 = lerp2(h2f(a[t][6]), h2f(a[t][7]), fr[t]);
            float2 eg0 = lerp2(e00, e01, fg[t]);
            float2 eg1 = lerp2(e10, e11, fg[t]);
            float2 ec  = lerp2(eg0, eg1, fb[t]);

            float z0 = __half2float(__ushort_as_half(z[t][0]));
            float z1 = __half2float(__ushort_as_half(z[t][1]));
            float z2 = __half2float(__ushort_as_half(z[t][2]));
            float z3 = __half2float(__ushort_as_half(z[t][3]));
            float z4 = __half2float(__ushort_as_half(z[t][4]));
            float z5 = __half2float(__ushort_as_half(z[t][5]));
            float z6 = __half2float(__ushort_as_half(z[t][6]));
            float z7 = __half2float(__ushort_as_half(z[t][7]));
            float s00 = fmaf(fr[t], z1 - z0, z0);
            float s01 = fmaf(fr[t], z3 - z2, z2);
            float s10 = fmaf(fr[t], z5 - z4, z4);
            float s11 = fmaf(fr[t], z7 - z6, z6);
            float sg0 = fmaf(fg[t], s01 - s00, s00);
            float sg1 = fmaf(fg[t], s11 - s10, s10);
            float sc  = fmaf(fb[t], sg1 - sg0, sg0);

            o0[t] = ec.x; o1[t] = ec.y; o2[t] = sc;
        }

        __stcs(op + jc,           make_float2(o0[0], o0[1]));
        __stcs(op + jc + HW2,     make_float2(o1[0], o1[1]));
        __stcs(op + jc + 2 * HW2, make_float2(o2[0], o2[1]));

        if (!more) break;
        v = vn;
        r2 = nr2; g2 = ng2; b2 = nb2;
    }
}

extern "C" void kernel_launch(void* const* d_in, const int* in_sizes, int n_in,
                              void* d_out, int out_size) {
    const float* x   = (const float*)d_in[0];   // (4,3,1080,1920) fp32
    const float* LUT = (const float*)d_in[1];   // (3,33,33,33) fp32
    float* out = (float*)d_out;

    static bool smem_ok = []() {
        cudaFuncSetAttribute(lut_apply_smem,
                             cudaFuncAttributeMaxDynamicSharedMemorySize,
                             SMEM_BYTES);
        return true;
    }();
    (void)smem_ok;

    pack_lut_kernel<<<(LUT_N + 255) / 256, 256>>>(LUT);
    lut_apply_smem<<<NBLOCKS, NTHREADS, SMEM_BYTES>>>(x, out);
}